// round 1
// baseline (speedup 1.0000x reference)
#include <cuda_runtime.h>
#include <cuda_bf16.h>

#define NROWS 8192
#define DIM   128
// log2(e) / TEMPERATURE = 1.4426950408889634 / 0.1
#define EXP_SCALE 14.426950408889634f

__device__ float g_f[NROWS * DIM];   // normalized features (scratch)
__device__ float g_pos[NROWS];
__device__ float g_all[NROWS];

// ---------------------------------------------------------------------------
// Kernel 1: L2-normalize rows, zero accumulators. One warp per row.
// ---------------------------------------------------------------------------
__global__ void cpe_norm_kernel(const float* __restrict__ feat) {
    int row  = blockIdx.x * 8 + (threadIdx.x >> 5);
    int lane = threadIdx.x & 31;
    const float4* src = (const float4*)(feat + (size_t)row * DIM);
    float4 v = src[lane];                       // 32 lanes x 4 = 128 elems
    float ss = v.x * v.x + v.y * v.y + v.z * v.z + v.w * v.w;
#pragma unroll
    for (int o = 16; o > 0; o >>= 1) ss += __shfl_xor_sync(0xffffffffu, ss, o);
    float inv = rsqrtf(fmaxf(ss, 1e-24f));      // norm = max(||x||, 1e-12)
    float4 o4 = make_float4(v.x * inv, v.y * inv, v.z * inv, v.w * inv);
    ((float4*)(g_f + (size_t)row * DIM))[lane] = o4;
    if (lane == 0) { g_pos[row] = 0.0f; g_all[row] = 0.0f; }
}

// ---------------------------------------------------------------------------
// Kernel 2: fused sim-GEMM + masked exp-sum reductions.
// Block: 256 threads (16x16), 128x128 output tile, 8x8 per-thread tile.
// grid.x = 64 row-tiles, grid.y = JSPLIT column splits.
// ---------------------------------------------------------------------------
#define BM 128
#define BK 16
#define JSPLIT 4
#define JT_PER_BLOCK (NROWS / BM / JSPLIT)   // 16

__device__ __forceinline__ float fast_ex2(float x) {
    float r;
    asm("ex2.approx.f32 %0, %1;" : "=f"(r) : "f"(x));
    return r;
}

__global__ __launch_bounds__(256, 2) void cpe_main_kernel(const int* __restrict__ labels) {
    __shared__ float As[BK][132];   // padded stride: conflict-free transpose stores
    __shared__ float Bs[BK][132];

    const int tid = threadIdx.x;
    const int tx = tid & 15;        // column group
    const int ty = tid >> 4;        // row group
    const int ibase = blockIdx.x * BM;

    int li[8];
#pragma unroll
    for (int r = 0; r < 8; r++) li[r] = __ldg(&labels[ibase + ty * 8 + r]);

    float pos[8], all[8];
#pragma unroll
    for (int r = 0; r < 8; r++) { pos[r] = 0.0f; all[r] = 0.0f; }

    const int lr = tid >> 2;        // 0..63   (tile row to load)
    const int lk = (tid & 3) * 4;   // 0,4,8,12 (k offset, float4)

    for (int jt = 0; jt < JT_PER_BLOCK; ++jt) {
        const int jbase = blockIdx.y * (JT_PER_BLOCK * BM) + jt * BM;

        float acc[8][8];
#pragma unroll
        for (int r = 0; r < 8; r++)
#pragma unroll
            for (int c = 0; c < 8; c++) acc[r][c] = 0.0f;

#pragma unroll 1
        for (int kc = 0; kc < DIM; kc += BK) {
            // global loads first (overlap latency with the barrier)
            float4 av0 = *(const float4*)&g_f[(size_t)(ibase + lr)      * DIM + kc + lk];
            float4 av1 = *(const float4*)&g_f[(size_t)(ibase + lr + 64) * DIM + kc + lk];
            float4 bv0 = *(const float4*)&g_f[(size_t)(jbase + lr)      * DIM + kc + lk];
            float4 bv1 = *(const float4*)&g_f[(size_t)(jbase + lr + 64) * DIM + kc + lk];

            __syncthreads();   // previous k-chunk reads done before overwrite
            As[lk + 0][lr] = av0.x; As[lk + 1][lr] = av0.y;
            As[lk + 2][lr] = av0.z; As[lk + 3][lr] = av0.w;
            As[lk + 0][lr + 64] = av1.x; As[lk + 1][lr + 64] = av1.y;
            As[lk + 2][lr + 64] = av1.z; As[lk + 3][lr + 64] = av1.w;
            Bs[lk + 0][lr] = bv0.x; Bs[lk + 1][lr] = bv0.y;
            Bs[lk + 2][lr] = bv0.z; Bs[lk + 3][lr] = bv0.w;
            Bs[lk + 0][lr + 64] = bv1.x; Bs[lk + 1][lr + 64] = bv1.y;
            Bs[lk + 2][lr + 64] = bv1.z; Bs[lk + 3][lr + 64] = bv1.w;
            __syncthreads();

#pragma unroll
            for (int kk = 0; kk < BK; kk++) {
                float4 a0 = *(const float4*)&As[kk][ty * 8];
                float4 a1 = *(const float4*)&As[kk][ty * 8 + 4];
                float4 b0 = *(const float4*)&Bs[kk][tx * 8];
                float4 b1 = *(const float4*)&Bs[kk][tx * 8 + 4];
                float a[8] = {a0.x, a0.y, a0.z, a0.w, a1.x, a1.y, a1.z, a1.w};
                float b[8] = {b0.x, b0.y, b0.z, b0.w, b1.x, b1.y, b1.z, b1.w};
#pragma unroll
                for (int r = 0; r < 8; r++)
#pragma unroll
                    for (int c = 0; c < 8; c++)
                        acc[r][c] += a[r] * b[c];
            }
        }

        // fused epilogue: masked exp accumulation (no max shift needed: the
        // shift cancels in pos/all and no clip can bind for |sim| <= 10)
#pragma unroll
        for (int c = 0; c < 8; c++) {
            const int j   = jbase + tx * 8 + c;
            const int ljc = __ldg(&labels[j]);
            const bool fgj = (ljc >= 0);
#pragma unroll
            for (int r = 0; r < 8; r++) {
                const int i = ibase + ty * 8 + r;
                float e = fast_ex2(acc[r][c] * EXP_SCALE);
                const bool w = fgj && (j != i);
                e = w ? e : 0.0f;
                all[r] += e;
                pos[r] += (w && (ljc == li[r])) ? e : 0.0f;
            }
        }
    }

#pragma unroll
    for (int r = 0; r < 8; r++) {
        const int i = ibase + ty * 8 + r;
        atomicAdd(&g_all[i], all[r]);
        atomicAdd(&g_pos[i], pos[r]);
    }
}

// ---------------------------------------------------------------------------
// Kernel 3: per-row loss + mean. Single block.
// ---------------------------------------------------------------------------
__global__ void cpe_final_kernel(const int* __restrict__ labels, float* __restrict__ out) {
    __shared__ float s_sum[256];
    __shared__ int   s_nv[256];
    __shared__ int   s_fg[256];

    float sum = 0.0f;
    int nv = 0, nfg = 0;
    for (int i = threadIdx.x; i < NROWS; i += 256) {
        const int lab = labels[i];
        const bool fg = (lab >= 0);
        if (fg) nfg++;
        const float p = g_pos[i];
        const float a = g_all[i];
        if (fg && p > 0.0f) {   // pos_count>0 <=> pos_sum>0 (exp never underflows to 0 here)
            float pc = fminf(fmaxf(p, 1e-6f), 1e6f);
            float ac = fminf(fmaxf(a, 1e-6f), 1e6f);
            float loss = fminf(__logf(ac) - __logf(pc), 10.0f);
            sum += loss;
            nv++;
        }
    }
    s_sum[threadIdx.x] = sum; s_nv[threadIdx.x] = nv; s_fg[threadIdx.x] = nfg;
    __syncthreads();
    for (int o = 128; o > 0; o >>= 1) {
        if (threadIdx.x < o) {
            s_sum[threadIdx.x] += s_sum[threadIdx.x + o];
            s_nv[threadIdx.x]  += s_nv[threadIdx.x + o];
            s_fg[threadIdx.x]  += s_fg[threadIdx.x + o];
        }
        __syncthreads();
    }
    if (threadIdx.x == 0) {
        const int   tnv  = s_nv[0];
        const int   tnfg = s_fg[0];
        const float mean = s_sum[0] / (float)(tnv > 0 ? tnv : 1);
        out[0] = (tnfg >= 2 && tnv > 0) ? mean : 0.0f;
    }
}

// ---------------------------------------------------------------------------
extern "C" void kernel_launch(void* const* d_in, const int* in_sizes, int n_in,
                              void* d_out, int out_size) {
    const float* features = (const float*)d_in[0];
    const int*   labels   = (const int*)d_in[1];
    float*       out      = (float*)d_out;

    cpe_norm_kernel<<<NROWS / 8, 256>>>(features);
    dim3 grid(NROWS / BM, JSPLIT);
    cpe_main_kernel<<<grid, 256>>>(labels);
    cpe_final_kernel<<<1, 256>>>(labels, out);
}

// round 3
// speedup vs baseline: 3.6917x; 3.6917x over previous
#include <cuda_runtime.h>
#include <cuda_bf16.h>
#include <cstdint>

#define NROWS 8192
#define DIM   128
#define KDIM  256                         // [hi(128) | lo(128)]
#define EXP_SCALE 14.426950408889634f     // log2(e)/0.1

#define TILE   128
#define NJT    8
#define GRID_X (NROWS / TILE)             // 64
#define GRID_Y (NROWS / (NJT * TILE))     // 8

// dynamic smem layout (bytes)
#define SM_A    0u
#define SM_B0   65536u
#define SM_B1   131072u
#define SM_JLAB 196608u
#define SM_TOTAL (196608 + NJT * TILE * 4)   // 200704

__device__ __nv_bfloat16 g_hl[NROWS * KDIM];   // normalized rows, hi|lo split
__device__ float g_pos[NROWS];
__device__ float g_all[NROWS];

// ============================ PTX helpers ============================
__device__ __forceinline__ uint32_t smem_u32(const void* p) {
    uint32_t a;
    asm("{ .reg .u64 t; cvta.to.shared.u64 t, %1; cvt.u32.u64 %0, t; }"
        : "=r"(a) : "l"(p));
    return a;
}
__device__ __forceinline__ float fast_ex2(float x) {
    float r; asm("ex2.approx.f32 %0, %1;" : "=f"(r) : "f"(x)); return r;
}
#define CP_ASYNC16(dst, src) \
    asm volatile("cp.async.cg.shared.global [%0], [%1], 16;" \
                 :: "r"(dst), "l"(src) : "memory")
#define CP_COMMIT() asm volatile("cp.async.commit_group;" ::: "memory")
#define CP_WAIT0()  asm volatile("cp.async.wait_group 0;" ::: "memory")

__device__ __forceinline__ void ldsm4(uint32_t* r, uint32_t addr) {
    asm volatile("ldmatrix.sync.aligned.m8n8.x4.shared.b16 {%0,%1,%2,%3}, [%4];"
                 : "=r"(r[0]), "=r"(r[1]), "=r"(r[2]), "=r"(r[3]) : "r"(addr));
}
__device__ __forceinline__ void mma16816(float* d, const uint32_t* a,
                                         uint32_t b0, uint32_t b1) {
    asm volatile(
        "mma.sync.aligned.m16n8k16.row.col.f32.bf16.bf16.f32 "
        "{%0,%1,%2,%3}, {%4,%5,%6,%7}, {%8,%9}, {%0,%1,%2,%3};"
        : "+f"(d[0]), "+f"(d[1]), "+f"(d[2]), "+f"(d[3])
        : "r"(a[0]), "r"(a[1]), "r"(a[2]), "r"(a[3]), "r"(b0), "r"(b1));
}

// Load a 128-row x 256-col bf16 tile into k-group-major smem:
// smem addr = (g*128 + row)*16, g = 16B k-group (0..31). 4096 cp.async of 16B.
__device__ __forceinline__ void load_tile(uint32_t dst, int rowbase, int tid) {
#pragma unroll
    for (int it = 0; it < 16; ++it) {
        int id = it * 256 + tid;          // 0..4095
        int g = id >> 7, r = id & 127;
        const __nv_bfloat16* src = g_hl + (size_t)(rowbase + r) * KDIM + g * 8;
        CP_ASYNC16(dst + (uint32_t)id * 16u, src);
    }
}

// ============================ Kernel 1: normalize + hi/lo split ============================
__global__ void cpe_norm_kernel(const float* __restrict__ feat) {
    int row  = blockIdx.x * 8 + (threadIdx.x >> 5);
    int lane = threadIdx.x & 31;
    float4 v = ((const float4*)(feat + (size_t)row * DIM))[lane];
    float ss = v.x * v.x + v.y * v.y + v.z * v.z + v.w * v.w;
#pragma unroll
    for (int o = 16; o > 0; o >>= 1) ss += __shfl_xor_sync(0xffffffffu, ss, o);
    float inv = rsqrtf(fmaxf(ss, 1e-24f));
    float x[4] = {v.x * inv, v.y * inv, v.z * inv, v.w * inv};
    __nv_bfloat16 h[4], l[4];
#pragma unroll
    for (int i = 0; i < 4; i++) {
        h[i] = __float2bfloat16(x[i]);
        l[i] = __float2bfloat16(x[i] - __bfloat162float(h[i]));
    }
    size_t base = (size_t)row * KDIM + lane * 4;
    __nv_bfloat162* hd = (__nv_bfloat162*)(g_hl + base);
    __nv_bfloat162* ld = (__nv_bfloat162*)(g_hl + base + DIM);
    hd[0] = __nv_bfloat162(h[0], h[1]); hd[1] = __nv_bfloat162(h[2], h[3]);
    ld[0] = __nv_bfloat162(l[0], l[1]); ld[1] = __nv_bfloat162(l[2], l[3]);
    if (lane == 0) { g_pos[row] = 0.0f; g_all[row] = 0.0f; }
}

// ============================ epilogue ============================
template <bool DIAG>
__device__ __forceinline__ void epi_tile(
    const float c[4][4][4], const int* jlab_t, int jb, int ibase,
    int m0, int n0, int lane,
    const int* li_lo, const int* li_hi,
    float* all_lo, float* all_hi, float* pos_lo, float* pos_hi)
{
#pragma unroll
    for (int n = 0; n < 4; ++n) {
        const int cl  = n0 + n * 8 + (lane & 3) * 2;
        const int lj0 = jlab_t[cl];
        const int lj1 = jlab_t[cl + 1];
        const int j0  = jb + cl;
        const int j1  = j0 + 1;
#pragma unroll
        for (int m = 0; m < 4; ++m) {
            const int i_lo = ibase + m0 + m * 16 + (lane >> 2);
            const int i_hi = i_lo + 8;
            float e0 = fast_ex2(c[m][n][0] * EXP_SCALE);
            float e1 = fast_ex2(c[m][n][1] * EXP_SCALE);
            float e2 = fast_ex2(c[m][n][2] * EXP_SCALE);
            float e3 = fast_ex2(c[m][n][3] * EXP_SCALE);
            const bool v0 = (lj0 >= 0) && (!DIAG || j0 != i_lo);
            const bool v1 = (lj1 >= 0) && (!DIAG || j1 != i_lo);
            const bool v2 = (lj0 >= 0) && (!DIAG || j0 != i_hi);
            const bool v3 = (lj1 >= 0) && (!DIAG || j1 != i_hi);
            e0 = v0 ? e0 : 0.0f; e1 = v1 ? e1 : 0.0f;
            e2 = v2 ? e2 : 0.0f; e3 = v3 ? e3 : 0.0f;
            all_lo[m] += e0 + e1;
            all_hi[m] += e2 + e3;
            pos_lo[m] += ((lj0 == li_lo[m]) ? e0 : 0.0f) + ((lj1 == li_lo[m]) ? e1 : 0.0f);
            pos_hi[m] += ((lj0 == li_hi[m]) ? e2 : 0.0f) + ((lj1 == li_hi[m]) ? e3 : 0.0f);
        }
    }
}

// ============================ Kernel 2: HMMA GEMM + fused epilogue ============================
__global__ __launch_bounds__(256, 1) void cpe_main_kernel(const int* __restrict__ labels) {
    extern __shared__ char smem[];
    const uint32_t sb = smem_u32(smem);
    int* jlab = (int*)(smem + SM_JLAB);

    const int tid  = threadIdx.x;
    const int lane = tid & 31;
    const int wid  = tid >> 5;
    const int m0   = (wid >> 2) * 64;     // warp row base within tile
    const int n0   = (wid & 3) * 32;      // warp col base within tile
    const int ibase  = blockIdx.x * TILE;
    const int jstart = blockIdx.y * (NJT * TILE);

    for (int t = tid; t < NJT * TILE; t += 256) jlab[t] = __ldg(&labels[jstart + t]);

    load_tile(sb + SM_A, ibase, tid);
    load_tile(sb + SM_B0, jstart, tid);
    CP_COMMIT();

    // row labels for this warp's 64 rows
    int li_lo[4], li_hi[4];
#pragma unroll
    for (int m = 0; m < 4; ++m) {
        li_lo[m] = __ldg(&labels[ibase + m0 + m * 16 + (lane >> 2)]);
        li_hi[m] = __ldg(&labels[ibase + m0 + m * 16 + (lane >> 2) + 8]);
    }

    // per-lane ldmatrix base offsets
    const int matid = lane >> 3, r = lane & 7;
    uint32_t a_base[4];
#pragma unroll
    for (int m = 0; m < 4; ++m)
        a_base[m] = sb + SM_A + (uint32_t)((matid >> 1) * 2048 +
                    (m0 + m * 16 + ((matid & 1) << 3) + r) * 16);
    // B: row index within tile for frag pair p: n0 + p*16 + ((matid>>1)<<3) + r, g += (matid&1)
    const uint32_t b_off0 = (uint32_t)((matid & 1) * 2048 + (n0 +      ((matid >> 1) << 3) + r) * 16);
    const uint32_t b_off1 = (uint32_t)((matid & 1) * 2048 + (n0 + 16 + ((matid >> 1) << 3) + r) * 16);

    float all_lo[4] = {0, 0, 0, 0}, all_hi[4] = {0, 0, 0, 0};
    float pos_lo[4] = {0, 0, 0, 0}, pos_hi[4] = {0, 0, 0, 0};

    CP_WAIT0();
    __syncthreads();

    for (int jt = 0; jt < NJT; ++jt) {
        const uint32_t SBc = sb + ((jt & 1) ? SM_B1 : SM_B0);
        const uint32_t SBn = sb + ((jt & 1) ? SM_B0 : SM_B1);
        if (jt + 1 < NJT) {
            load_tile(SBn, jstart + (jt + 1) * TILE, tid);
            CP_COMMIT();
        }

        float c[4][4][4];
#pragma unroll
        for (int m = 0; m < 4; ++m)
#pragma unroll
            for (int n = 0; n < 4; ++n)
#pragma unroll
                for (int k = 0; k < 4; ++k) c[m][n][k] = 0.0f;

#pragma unroll 4
        for (int ks = 0; ks < 16; ++ks) {
            const uint32_t kadv = (uint32_t)ks * 4096u;
            uint32_t af[4][4];
#pragma unroll
            for (int m = 0; m < 4; ++m) ldsm4(af[m], a_base[m] + kadv);
            uint32_t bf0[4], bf1[4];
            ldsm4(bf0, SBc + b_off0 + kadv);
            ldsm4(bf1, SBc + b_off1 + kadv);
#pragma unroll
            for (int m = 0; m < 4; ++m) {
                mma16816(c[m][0], af[m], bf0[0], bf0[1]);
                mma16816(c[m][1], af[m], bf0[2], bf0[3]);
                mma16816(c[m][2], af[m], bf1[0], bf1[1]);
                mma16816(c[m][3], af[m], bf1[2], bf1[3]);
            }
        }

        const int jb = jstart + jt * TILE;
        if (jb == ibase)
            epi_tile<true >(c, jlab + jt * TILE, jb, ibase, m0, n0, lane,
                            li_lo, li_hi, all_lo, all_hi, pos_lo, pos_hi);
        else
            epi_tile<false>(c, jlab + jt * TILE, jb, ibase, m0, n0, lane,
                            li_lo, li_hi, all_lo, all_hi, pos_lo, pos_hi);

        if (jt + 1 < NJT) {
            CP_WAIT0();
            __syncthreads();
        }
    }

    // reduce across the 4 lanes that share each row slot
#pragma unroll
    for (int m = 0; m < 4; ++m) {
#pragma unroll
        for (int o = 1; o <= 2; o <<= 1) {
            all_lo[m] += __shfl_xor_sync(0xffffffffu, all_lo[m], o);
            all_hi[m] += __shfl_xor_sync(0xffffffffu, all_hi[m], o);
            pos_lo[m] += __shfl_xor_sync(0xffffffffu, pos_lo[m], o);
            pos_hi[m] += __shfl_xor_sync(0xffffffffu, pos_hi[m], o);
        }
    }
    if ((lane & 3) == 0) {
#pragma unroll
        for (int m = 0; m < 4; ++m) {
            const int rr = ibase + m0 + m * 16 + (lane >> 2);
            atomicAdd(&g_all[rr],     all_lo[m]);
            atomicAdd(&g_pos[rr],     pos_lo[m]);
            atomicAdd(&g_all[rr + 8], all_hi[m]);
            atomicAdd(&g_pos[rr + 8], pos_hi[m]);
        }
    }
}

// ============================ Kernel 3: reduce ============================
__global__ void cpe_final_kernel(const int* __restrict__ labels, float* __restrict__ out) {
    __shared__ float s_sum[256];
    __shared__ int   s_nv[256];
    __shared__ int   s_fg[256];
    float sum = 0.0f; int nv = 0, nfg = 0;
    for (int i = threadIdx.x; i < NROWS; i += 256) {
        const int lab = labels[i];
        const bool fg = (lab >= 0);
        if (fg) nfg++;
        const float p = g_pos[i];
        const float a = g_all[i];
        if (fg && p > 0.0f) {
            float pc = fminf(fmaxf(p, 1e-6f), 1e6f);
            float ac = fminf(fmaxf(a, 1e-6f), 1e6f);
            sum += fminf(__logf(ac) - __logf(pc), 10.0f);
            nv++;
        }
    }
    s_sum[threadIdx.x] = sum; s_nv[threadIdx.x] = nv; s_fg[threadIdx.x] = nfg;
    __syncthreads();
    for (int o = 128; o > 0; o >>= 1) {
        if (threadIdx.x < o) {
            s_sum[threadIdx.x] += s_sum[threadIdx.x + o];
            s_nv[threadIdx.x]  += s_nv[threadIdx.x + o];
            s_fg[threadIdx.x]  += s_fg[threadIdx.x + o];
        }
        __syncthreads();
    }
    if (threadIdx.x == 0) {
        const int tnv = s_nv[0], tnfg = s_fg[0];
        const float mean = s_sum[0] / (float)(tnv > 0 ? tnv : 1);
        out[0] = (tnfg >= 2 && tnv > 0) ? mean : 0.0f;
    }
}

// ============================================================================
extern "C" void kernel_launch(void* const* d_in, const int* in_sizes, int n_in,
                              void* d_out, int out_size) {
    const float* features = (const float*)d_in[0];
    const int*   labels   = (const int*)d_in[1];
    float*       out      = (float*)d_out;

    cudaFuncSetAttribute(cpe_main_kernel,
                         cudaFuncAttributeMaxDynamicSharedMemorySize, SM_TOTAL);

    cpe_norm_kernel<<<NROWS / 8, 256>>>(features);
    cpe_main_kernel<<<dim3(GRID_X, GRID_Y), 256, SM_TOTAL>>>(labels);
    cpe_final_kernel<<<1, 256>>>(labels, out);
}

// round 4
// speedup vs baseline: 7.0704x; 1.9152x over previous
#include <cuda_runtime.h>
#include <cuda_bf16.h>
#include <cstdint>

#define NROWS 8192
#define DIM   128
#define KDIM  128
// sqrt(log2(e)/0.1) — baked into both operands so acc = sim*log2(e)/T
#define ROOT_SCALE 3.79828255588053f

#define TILE   128
#define NJT    8
#define GRID_X (NROWS / TILE)             // 64
#define GRID_Y (NROWS / (NJT * TILE))     // 8

// dynamic smem layout (bytes): A 32K | B0 32K | B1 32K | jlab 4K
#define SM_A    0u
#define SM_B0   32768u
#define SM_B1   65536u
#define SM_JLAB 98304u
#define SM_TOTAL (98304 + NJT * TILE * 4)   // 102400

__device__ __nv_bfloat16 g_hi[NROWS * KDIM];   // normalized * ROOT_SCALE, bf16
__device__ float g_pos[NROWS];
__device__ float g_all[NROWS];

// ============================ PTX helpers ============================
__device__ __forceinline__ uint32_t smem_u32(const void* p) {
    uint32_t a;
    asm("{ .reg .u64 t; cvta.to.shared.u64 t, %1; cvt.u32.u64 %0, t; }"
        : "=r"(a) : "l"(p));
    return a;
}
__device__ __forceinline__ float fast_ex2(float x) {
    float r; asm("ex2.approx.f32 %0, %1;" : "=f"(r) : "f"(x)); return r;
}
#define CP_ASYNC16(dst, src) \
    asm volatile("cp.async.cg.shared.global [%0], [%1], 16;" \
                 :: "r"(dst), "l"(src) : "memory")
#define CP_COMMIT() asm volatile("cp.async.commit_group;" ::: "memory")
#define CP_WAIT0()  asm volatile("cp.async.wait_group 0;" ::: "memory")

__device__ __forceinline__ void ldsm4(uint32_t* r, uint32_t addr) {
    asm volatile("ldmatrix.sync.aligned.m8n8.x4.shared.b16 {%0,%1,%2,%3}, [%4];"
                 : "=r"(r[0]), "=r"(r[1]), "=r"(r[2]), "=r"(r[3]) : "r"(addr));
}
__device__ __forceinline__ void mma16816(float* d, const uint32_t* a,
                                         uint32_t b0, uint32_t b1) {
    asm volatile(
        "mma.sync.aligned.m16n8k16.row.col.f32.bf16.bf16.f32 "
        "{%0,%1,%2,%3}, {%4,%5,%6,%7}, {%8,%9}, {%0,%1,%2,%3};"
        : "+f"(d[0]), "+f"(d[1]), "+f"(d[2]), "+f"(d[3])
        : "r"(a[0]), "r"(a[1]), "r"(a[2]), "r"(a[3]), "r"(b0), "r"(b1));
}

// Load a 128-row x 128-col bf16 tile, k-group-major:
// smem addr = (g*128 + row)*16, g = 16B k-group (0..15). 2048 cp.async of 16B.
__device__ __forceinline__ void load_tile(uint32_t dst, int rowbase, int tid) {
#pragma unroll
    for (int it = 0; it < 8; ++it) {
        int id = it * 256 + tid;          // 0..2047
        int g = id >> 7, r = id & 127;
        const __nv_bfloat16* src = g_hi + (size_t)(rowbase + r) * KDIM + g * 8;
        CP_ASYNC16(dst + (uint32_t)id * 16u, src);
    }
}

// ============================ Kernel 1: normalize (scaled) ============================
__global__ void cpe_norm_kernel(const float* __restrict__ feat) {
    int row  = blockIdx.x * 8 + (threadIdx.x >> 5);
    int lane = threadIdx.x & 31;
    float4 v = ((const float4*)(feat + (size_t)row * DIM))[lane];
    float ss = v.x * v.x + v.y * v.y + v.z * v.z + v.w * v.w;
#pragma unroll
    for (int o = 16; o > 0; o >>= 1) ss += __shfl_xor_sync(0xffffffffu, ss, o);
    float inv = rsqrtf(fmaxf(ss, 1e-24f)) * ROOT_SCALE;
    __nv_bfloat16 h[4];
    h[0] = __float2bfloat16(v.x * inv);
    h[1] = __float2bfloat16(v.y * inv);
    h[2] = __float2bfloat16(v.z * inv);
    h[3] = __float2bfloat16(v.w * inv);
    __nv_bfloat162* hd = (__nv_bfloat162*)(g_hi + (size_t)row * KDIM + lane * 4);
    hd[0] = __nv_bfloat162(h[0], h[1]);
    hd[1] = __nv_bfloat162(h[2], h[3]);
    if (lane == 0) { g_pos[row] = 0.0f; g_all[row] = 0.0f; }
}

// ============================ epilogue ============================
template <bool DIAG>
__device__ __forceinline__ void epi_tile(
    const float c[4][4][4], const int* jlab_t, int jb, int ibase,
    int m0, int n0, int lane,
    const int* li_lo, const int* li_hi,
    float* all_lo, float* all_hi, float* pos_lo, float* pos_hi)
{
#pragma unroll
    for (int n = 0; n < 4; ++n) {
        const int cl  = n0 + n * 8 + (lane & 3) * 2;
        const int lj0 = jlab_t[cl];
        const int lj1 = jlab_t[cl + 1];
        const int j0  = jb + cl;
        const int j1  = j0 + 1;
#pragma unroll
        for (int m = 0; m < 4; ++m) {
            const int i_lo = ibase + m0 + m * 16 + (lane >> 2);
            const int i_hi = i_lo + 8;
            float e0 = fast_ex2(c[m][n][0]);
            float e1 = fast_ex2(c[m][n][1]);
            float e2 = fast_ex2(c[m][n][2]);
            float e3 = fast_ex2(c[m][n][3]);
            const bool v0 = (lj0 >= 0) && (!DIAG || j0 != i_lo);
            const bool v1 = (lj1 >= 0) && (!DIAG || j1 != i_lo);
            const bool v2 = (lj0 >= 0) && (!DIAG || j0 != i_hi);
            const bool v3 = (lj1 >= 0) && (!DIAG || j1 != i_hi);
            e0 = v0 ? e0 : 0.0f; e1 = v1 ? e1 : 0.0f;
            e2 = v2 ? e2 : 0.0f; e3 = v3 ? e3 : 0.0f;
            all_lo[m] += e0 + e1;
            all_hi[m] += e2 + e3;
            pos_lo[m] += ((lj0 == li_lo[m]) ? e0 : 0.0f) + ((lj1 == li_lo[m]) ? e1 : 0.0f);
            pos_hi[m] += ((lj0 == li_hi[m]) ? e2 : 0.0f) + ((lj1 == li_hi[m]) ? e3 : 0.0f);
        }
    }
}

// ============================ Kernel 2: HMMA GEMM + fused epilogue ============================
__global__ __launch_bounds__(256, 2) void cpe_main_kernel(const int* __restrict__ labels) {
    extern __shared__ char smem[];
    const uint32_t sb = smem_u32(smem);
    int* jlab = (int*)(smem + SM_JLAB);

    const int tid  = threadIdx.x;
    const int lane = tid & 31;
    const int wid  = tid >> 5;
    const int m0   = (wid >> 2) * 64;     // warp row base within tile
    const int n0   = (wid & 3) * 32;      // warp col base within tile
    const int ibase  = blockIdx.x * TILE;
    const int jstart = blockIdx.y * (NJT * TILE);

    for (int t = tid; t < NJT * TILE; t += 256) jlab[t] = __ldg(&labels[jstart + t]);

    load_tile(sb + SM_A, ibase, tid);
    load_tile(sb + SM_B0, jstart, tid);
    CP_COMMIT();

    int li_lo[4], li_hi[4];
#pragma unroll
    for (int m = 0; m < 4; ++m) {
        li_lo[m] = __ldg(&labels[ibase + m0 + m * 16 + (lane >> 2)]);
        li_hi[m] = __ldg(&labels[ibase + m0 + m * 16 + (lane >> 2) + 8]);
    }

    // per-lane ldmatrix base offsets (k-group-major layout, 2048B per k-group)
    const int matid = lane >> 3, r = lane & 7;
    uint32_t a_base[4];
#pragma unroll
    for (int m = 0; m < 4; ++m)
        a_base[m] = sb + SM_A + (uint32_t)((matid >> 1) * 2048 +
                    (m0 + m * 16 + ((matid & 1) << 3) + r) * 16);
    const uint32_t b_off0 = (uint32_t)((matid & 1) * 2048 + (n0 +      ((matid >> 1) << 3) + r) * 16);
    const uint32_t b_off1 = (uint32_t)((matid & 1) * 2048 + (n0 + 16 + ((matid >> 1) << 3) + r) * 16);

    float all_lo[4] = {0, 0, 0, 0}, all_hi[4] = {0, 0, 0, 0};
    float pos_lo[4] = {0, 0, 0, 0}, pos_hi[4] = {0, 0, 0, 0};

    CP_WAIT0();
    __syncthreads();

    for (int jt = 0; jt < NJT; ++jt) {
        const uint32_t SBc = sb + ((jt & 1) ? SM_B1 : SM_B0);
        const uint32_t SBn = sb + ((jt & 1) ? SM_B0 : SM_B1);
        if (jt + 1 < NJT) {
            load_tile(SBn, jstart + (jt + 1) * TILE, tid);
            CP_COMMIT();
        }

        float c[4][4][4];
#pragma unroll
        for (int m = 0; m < 4; ++m)
#pragma unroll
            for (int n = 0; n < 4; ++n)
#pragma unroll
                for (int k = 0; k < 4; ++k) c[m][n][k] = 0.0f;

#pragma unroll
        for (int ks = 0; ks < 8; ++ks) {
            const uint32_t kadv = (uint32_t)ks * 4096u;   // 2 k-groups per ks
            uint32_t af[4][4];
#pragma unroll
            for (int m = 0; m < 4; ++m) ldsm4(af[m], a_base[m] + kadv);
            uint32_t bf0[4], bf1[4];
            ldsm4(bf0, SBc + b_off0 + kadv);
            ldsm4(bf1, SBc + b_off1 + kadv);
#pragma unroll
            for (int m = 0; m < 4; ++m) {
                mma16816(c[m][0], af[m], bf0[0], bf0[1]);
                mma16816(c[m][1], af[m], bf0[2], bf0[3]);
                mma16816(c[m][2], af[m], bf1[0], bf1[1]);
                mma16816(c[m][3], af[m], bf1[2], bf1[3]);
            }
        }

        const int jb = jstart + jt * TILE;
        if (jb == ibase)
            epi_tile<true >(c, jlab + jt * TILE, jb, ibase, m0, n0, lane,
                            li_lo, li_hi, all_lo, all_hi, pos_lo, pos_hi);
        else
            epi_tile<false>(c, jlab + jt * TILE, jb, ibase, m0, n0, lane,
                            li_lo, li_hi, all_lo, all_hi, pos_lo, pos_hi);

        if (jt + 1 < NJT) {
            CP_WAIT0();
            __syncthreads();
        }
    }

    // reduce across the 4 lanes sharing each row slot
#pragma unroll
    for (int m = 0; m < 4; ++m) {
#pragma unroll
        for (int o = 1; o <= 2; o <<= 1) {
            all_lo[m] += __shfl_xor_sync(0xffffffffu, all_lo[m], o);
            all_hi[m] += __shfl_xor_sync(0xffffffffu, all_hi[m], o);
            pos_lo[m] += __shfl_xor_sync(0xffffffffu, pos_lo[m], o);
            pos_hi[m] += __shfl_xor_sync(0xffffffffu, pos_hi[m], o);
        }
    }
    if ((lane & 3) == 0) {
#pragma unroll
        for (int m = 0; m < 4; ++m) {
            const int rr = ibase + m0 + m * 16 + (lane >> 2);
            atomicAdd(&g_all[rr],     all_lo[m]);
            atomicAdd(&g_pos[rr],     pos_lo[m]);
            atomicAdd(&g_all[rr + 8], all_hi[m]);
            atomicAdd(&g_pos[rr + 8], pos_hi[m]);
        }
    }
}

// ============================ Kernel 3: reduce ============================
__global__ void cpe_final_kernel(const int* __restrict__ labels, float* __restrict__ out) {
    __shared__ float s_sum[1024];
    __shared__ int   s_nv[1024];
    __shared__ int   s_fg[1024];
    float sum = 0.0f; int nv = 0, nfg = 0;
    for (int i = threadIdx.x; i < NROWS; i += 1024) {
        const int lab = labels[i];
        const bool fg = (lab >= 0);
        if (fg) nfg++;
        const float p = g_pos[i];
        const float a = g_all[i];
        if (fg && p > 0.0f) {
            float pc = fminf(fmaxf(p, 1e-6f), 1e6f);
            float ac = fminf(fmaxf(a, 1e-6f), 1e6f);
            sum += fminf(__logf(ac) - __logf(pc), 10.0f);
            nv++;
        }
    }
    s_sum[threadIdx.x] = sum; s_nv[threadIdx.x] = nv; s_fg[threadIdx.x] = nfg;
    __syncthreads();
    for (int o = 512; o > 0; o >>= 1) {
        if (threadIdx.x < o) {
            s_sum[threadIdx.x] += s_sum[threadIdx.x + o];
            s_nv[threadIdx.x]  += s_nv[threadIdx.x + o];
            s_fg[threadIdx.x]  += s_fg[threadIdx.x + o];
        }
        __syncthreads();
    }
    if (threadIdx.x == 0) {
        const int tnv = s_nv[0], tnfg = s_fg[0];
        const float mean = s_sum[0] / (float)(tnv > 0 ? tnv : 1);
        out[0] = (tnfg >= 2 && tnv > 0) ? mean : 0.0f;
    }
}

// ============================================================================
extern "C" void kernel_launch(void* const* d_in, const int* in_sizes, int n_in,
                              void* d_out, int out_size) {
    const float* features = (const float*)d_in[0];
    const int*   labels   = (const int*)d_in[1];
    float*       out      = (float*)d_out;

    cudaFuncSetAttribute(cpe_main_kernel,
                         cudaFuncAttributeMaxDynamicSharedMemorySize, SM_TOTAL);

    cpe_norm_kernel<<<NROWS / 8, 256>>>(features);
    cpe_main_kernel<<<dim3(GRID_X, GRID_Y), 256, SM_TOTAL>>>(labels);
    cpe_final_kernel<<<1, 1024>>>(labels, out);
}

// round 5
// speedup vs baseline: 10.2448x; 1.4490x over previous
#include <cuda_runtime.h>
#include <cuda_bf16.h>
#include <cstdint>

#define NROWS 8192
#define DIM   128
#define KDIM  128
// sqrt(log2(e)/0.1) — baked into both operands so acc = sim*log2(e)/T
#define ROOT_SCALE 3.79828255588053f

#define TILE    128
#define NTILES  (NROWS / TILE)            // 64

// dynamic smem layout (bytes): A 32K | B0 32K | B1 32K
#define SM_A    0u
#define SM_B0   32768u
#define SM_B1   65536u
#define SM_TOTAL 98304

__device__ __nv_bfloat16 g_hi[NROWS * KDIM];   // normalized * ROOT_SCALE, bf16
__device__ float g_pos[NROWS];
__device__ float g_all[NROWS];

// ============================ PTX helpers ============================
__device__ __forceinline__ uint32_t smem_u32(const void* p) {
    uint32_t a;
    asm("{ .reg .u64 t; cvta.to.shared.u64 t, %1; cvt.u32.u64 %0, t; }"
        : "=r"(a) : "l"(p));
    return a;
}
__device__ __forceinline__ float fast_ex2(float x) {
    float r; asm("ex2.approx.f32 %0, %1;" : "=f"(r) : "f"(x)); return r;
}
#define CP_ASYNC16(dst, src) \
    asm volatile("cp.async.cg.shared.global [%0], [%1], 16;" \
                 :: "r"(dst), "l"(src) : "memory")
#define CP_COMMIT() asm volatile("cp.async.commit_group;" ::: "memory")
#define CP_WAIT0()  asm volatile("cp.async.wait_group 0;" ::: "memory")

__device__ __forceinline__ void ldsm4(uint32_t* r, uint32_t addr) {
    asm volatile("ldmatrix.sync.aligned.m8n8.x4.shared.b16 {%0,%1,%2,%3}, [%4];"
                 : "=r"(r[0]), "=r"(r[1]), "=r"(r[2]), "=r"(r[3]) : "r"(addr));
}
__device__ __forceinline__ void mma16816(float* d, const uint32_t* a,
                                         uint32_t b0, uint32_t b1) {
    asm volatile(
        "mma.sync.aligned.m16n8k16.row.col.f32.bf16.bf16.f32 "
        "{%0,%1,%2,%3}, {%4,%5,%6,%7}, {%8,%9}, {%0,%1,%2,%3};"
        : "+f"(d[0]), "+f"(d[1]), "+f"(d[2]), "+f"(d[3])
        : "r"(a[0]), "r"(a[1]), "r"(a[2]), "r"(a[3]), "r"(b0), "r"(b1));
}

// Load a 128-row x 128-col bf16 tile, k-group-major:
// smem addr = (g*128 + row)*16, g = 16B k-group (0..15). 2048 cp.async of 16B.
__device__ __forceinline__ void load_tile(uint32_t dst, int rowbase, int tid) {
#pragma unroll
    for (int it = 0; it < 8; ++it) {
        int id = it * 256 + tid;          // 0..2047
        int g = id >> 7, r = id & 127;
        const __nv_bfloat16* src = g_hi + (size_t)(rowbase + r) * KDIM + g * 8;
        CP_ASYNC16(dst + (uint32_t)id * 16u, src);
    }
}

// ============================ Kernel 1: normalize (scaled), 2 rows/warp ============================
__global__ void cpe_norm_kernel(const float* __restrict__ feat) {
    int row0 = blockIdx.x * 16 + (threadIdx.x >> 5) * 2;
    int lane = threadIdx.x & 31;
    float4 v0 = ((const float4*)(feat + (size_t)row0 * DIM))[lane];
    float4 v1 = ((const float4*)(feat + (size_t)(row0 + 1) * DIM))[lane];
    float s0 = v0.x * v0.x + v0.y * v0.y + v0.z * v0.z + v0.w * v0.w;
    float s1 = v1.x * v1.x + v1.y * v1.y + v1.z * v1.z + v1.w * v1.w;
#pragma unroll
    for (int o = 16; o > 0; o >>= 1) {
        s0 += __shfl_xor_sync(0xffffffffu, s0, o);
        s1 += __shfl_xor_sync(0xffffffffu, s1, o);
    }
    float i0 = rsqrtf(fmaxf(s0, 1e-24f)) * ROOT_SCALE;
    float i1 = rsqrtf(fmaxf(s1, 1e-24f)) * ROOT_SCALE;
    __nv_bfloat162* hd0 = (__nv_bfloat162*)(g_hi + (size_t)row0 * KDIM + lane * 4);
    __nv_bfloat162* hd1 = (__nv_bfloat162*)(g_hi + (size_t)(row0 + 1) * KDIM + lane * 4);
    hd0[0] = __nv_bfloat162(__float2bfloat16(v0.x * i0), __float2bfloat16(v0.y * i0));
    hd0[1] = __nv_bfloat162(__float2bfloat16(v0.z * i0), __float2bfloat16(v0.w * i0));
    hd1[0] = __nv_bfloat162(__float2bfloat16(v1.x * i1), __float2bfloat16(v1.y * i1));
    hd1[1] = __nv_bfloat162(__float2bfloat16(v1.z * i1), __float2bfloat16(v1.w * i1));
    if (lane == 0) {
        g_pos[row0] = 0.0f; g_all[row0] = 0.0f;
        g_pos[row0 + 1] = 0.0f; g_all[row0 + 1] = 0.0f;
    }
}

// ============================ epilogues ============================
// Diagonal tile: row sums only, self-exclusion mask.
__device__ __forceinline__ void epi_diag(
    const float c[4][4][4], const int* __restrict__ labels, int jb, int ibase,
    int m0, int n0, int lane,
    const int* li_lo, const int* li_hi,
    float* all_lo, float* all_hi, float* pos_lo, float* pos_hi)
{
#pragma unroll
    for (int n = 0; n < 4; ++n) {
        const int cl  = n0 + n * 8 + (lane & 3) * 2;
        const int lj0 = __ldg(&labels[jb + cl]);
        const int lj1 = __ldg(&labels[jb + cl + 1]);
        const int j0  = jb + cl;
        const int j1  = j0 + 1;
#pragma unroll
        for (int m = 0; m < 4; ++m) {
            const int i_lo = ibase + m0 + m * 16 + (lane >> 2);
            const int i_hi = i_lo + 8;
            float e0 = fast_ex2(c[m][n][0]);
            float e1 = fast_ex2(c[m][n][1]);
            float e2 = fast_ex2(c[m][n][2]);
            float e3 = fast_ex2(c[m][n][3]);
            e0 = ((lj0 >= 0) && (j0 != i_lo)) ? e0 : 0.0f;
            e1 = ((lj1 >= 0) && (j1 != i_lo)) ? e1 : 0.0f;
            e2 = ((lj0 >= 0) && (j0 != i_hi)) ? e2 : 0.0f;
            e3 = ((lj1 >= 0) && (j1 != i_hi)) ? e3 : 0.0f;
            all_lo[m] += e0 + e1;
            all_hi[m] += e2 + e3;
            pos_lo[m] += ((lj0 == li_lo[m]) ? e0 : 0.0f) + ((lj1 == li_lo[m]) ? e1 : 0.0f);
            pos_hi[m] += ((lj0 == li_hi[m]) ? e2 : 0.0f) + ((lj1 == li_hi[m]) ? e3 : 0.0f);
        }
    }
}

// Off-diagonal tile: row sums (masked by fg[j]) AND column sums (masked by fg[i]).
__device__ __forceinline__ void epi_offdiag(
    const float c[4][4][4], const int* __restrict__ labels, int jb, int ibase,
    int m0, int n0, int lane,
    const int* li_lo, const int* li_hi,
    float* all_lo, float* all_hi, float* pos_lo, float* pos_hi)
{
    float ca0[4] = {0, 0, 0, 0}, ca1[4] = {0, 0, 0, 0};
    float cp0[4] = {0, 0, 0, 0}, cp1[4] = {0, 0, 0, 0};
#pragma unroll
    for (int n = 0; n < 4; ++n) {
        const int cl  = n0 + n * 8 + (lane & 3) * 2;
        const int lj0 = __ldg(&labels[jb + cl]);
        const int lj1 = __ldg(&labels[jb + cl + 1]);
        const bool f0 = (lj0 >= 0), f1 = (lj1 >= 0);
#pragma unroll
        for (int m = 0; m < 4; ++m) {
            const bool glo = (li_lo[m] >= 0), ghi = (li_hi[m] >= 0);
            const float e0 = fast_ex2(c[m][n][0]);
            const float e1 = fast_ex2(c[m][n][1]);
            const float e2 = fast_ex2(c[m][n][2]);
            const float e3 = fast_ex2(c[m][n][3]);
            // row contributions (mask fg[j]; i != j guaranteed off-diagonal)
            const float r0 = f0 ? e0 : 0.0f, r1 = f1 ? e1 : 0.0f;
            const float r2 = f0 ? e2 : 0.0f, r3 = f1 ? e3 : 0.0f;
            all_lo[m] += r0 + r1;
            all_hi[m] += r2 + r3;
            pos_lo[m] += ((lj0 == li_lo[m]) ? r0 : 0.0f) + ((lj1 == li_lo[m]) ? r1 : 0.0f);
            pos_hi[m] += ((lj0 == li_hi[m]) ? r2 : 0.0f) + ((lj1 == li_hi[m]) ? r3 : 0.0f);
            // column contributions (mask fg[i])
            const float q0 = glo ? e0 : 0.0f, q2 = ghi ? e2 : 0.0f;
            const float q1 = glo ? e1 : 0.0f, q3 = ghi ? e3 : 0.0f;
            ca0[n] += q0 + q2;
            ca1[n] += q1 + q3;
            cp0[n] += ((lj0 == li_lo[m]) ? q0 : 0.0f) + ((lj0 == li_hi[m]) ? q2 : 0.0f);
            cp1[n] += ((lj1 == li_lo[m]) ? q1 : 0.0f) + ((lj1 == li_hi[m]) ? q3 : 0.0f);
        }
    }
    // reduce column partials across the 8 lanes sharing each column (lane>>2 axis)
#pragma unroll
    for (int n = 0; n < 4; ++n) {
#pragma unroll
        for (int o = 4; o <= 16; o <<= 1) {
            ca0[n] += __shfl_xor_sync(0xffffffffu, ca0[n], o);
            ca1[n] += __shfl_xor_sync(0xffffffffu, ca1[n], o);
            cp0[n] += __shfl_xor_sync(0xffffffffu, cp0[n], o);
            cp1[n] += __shfl_xor_sync(0xffffffffu, cp1[n], o);
        }
    }
    if (lane < 4) {
#pragma unroll
        for (int n = 0; n < 4; ++n) {
            const int j0 = jb + n0 + n * 8 + lane * 2;
            atomicAdd(&g_all[j0],     ca0[n]);
            atomicAdd(&g_pos[j0],     cp0[n]);
            atomicAdd(&g_all[j0 + 1], ca1[n]);
            atomicAdd(&g_pos[j0 + 1], cp1[n]);
        }
    }
}

// ============================ Kernel 2: symmetric HMMA GEMM + fused epilogue ============================
__global__ __launch_bounds__(256, 2) void cpe_main_kernel(const int* __restrict__ labels) {
    extern __shared__ char smem[];
    const uint32_t sb = smem_u32(smem);

    const int tid  = threadIdx.x;
    const int lane = tid & 31;
    const int wid  = tid >> 5;
    const int m0   = (wid >> 2) * 64;     // warp row base within tile
    const int n0   = (wid & 3) * 32;      // warp col base within tile
    const int It   = blockIdx.x;          // i-tile index
    const int grp  = blockIdx.y;          // s-group
    const int ibase = It * TILE;

    // tiles this CTA owns: s = grp*8 + t;  g=3 additionally gets s=32 when It<32
    const int nt = (grp == 3 && It < 32) ? 9 : 8;

    load_tile(sb + SM_A, ibase, tid);
    load_tile(sb + SM_B0, ((It + grp * 8) & (NTILES - 1)) * TILE, tid);
    CP_COMMIT();

    int li_lo[4], li_hi[4];
#pragma unroll
    for (int m = 0; m < 4; ++m) {
        li_lo[m] = __ldg(&labels[ibase + m0 + m * 16 + (lane >> 2)]);
        li_hi[m] = __ldg(&labels[ibase + m0 + m * 16 + (lane >> 2) + 8]);
    }

    // per-lane ldmatrix base offsets (k-group-major layout, 2048B per k-group)
    const int matid = lane >> 3, r = lane & 7;
    uint32_t a_base[4];
#pragma unroll
    for (int m = 0; m < 4; ++m)
        a_base[m] = sb + SM_A + (uint32_t)((matid >> 1) * 2048 +
                    (m0 + m * 16 + ((matid & 1) << 3) + r) * 16);
    const uint32_t b_off0 = (uint32_t)((matid & 1) * 2048 + (n0 +      ((matid >> 1) << 3) + r) * 16);
    const uint32_t b_off1 = (uint32_t)((matid & 1) * 2048 + (n0 + 16 + ((matid >> 1) << 3) + r) * 16);

    float all_lo[4] = {0, 0, 0, 0}, all_hi[4] = {0, 0, 0, 0};
    float pos_lo[4] = {0, 0, 0, 0}, pos_hi[4] = {0, 0, 0, 0};

    CP_WAIT0();
    __syncthreads();

    for (int t = 0; t < nt; ++t) {
        const int s = grp * 8 + t;
        const int jb = ((It + s) & (NTILES - 1)) * TILE;
        const uint32_t SBc = sb + ((t & 1) ? SM_B1 : SM_B0);
        const uint32_t SBn = sb + ((t & 1) ? SM_B0 : SM_B1);
        if (t + 1 < nt) {
            load_tile(SBn, ((It + s + 1) & (NTILES - 1)) * TILE, tid);
            CP_COMMIT();
        }

        float c[4][4][4];
#pragma unroll
        for (int m = 0; m < 4; ++m)
#pragma unroll
            for (int n = 0; n < 4; ++n)
#pragma unroll
                for (int k = 0; k < 4; ++k) c[m][n][k] = 0.0f;

#pragma unroll
        for (int ks = 0; ks < 8; ++ks) {
            const uint32_t kadv = (uint32_t)ks * 4096u;   // 2 k-groups per ks
            uint32_t af[4][4];
#pragma unroll
            for (int m = 0; m < 4; ++m) ldsm4(af[m], a_base[m] + kadv);
            uint32_t bf0[4], bf1[4];
            ldsm4(bf0, SBc + b_off0 + kadv);
            ldsm4(bf1, SBc + b_off1 + kadv);
#pragma unroll
            for (int m = 0; m < 4; ++m) {
                mma16816(c[m][0], af[m], bf0[0], bf0[1]);
                mma16816(c[m][1], af[m], bf0[2], bf0[3]);
                mma16816(c[m][2], af[m], bf1[0], bf1[1]);
                mma16816(c[m][3], af[m], bf1[2], bf1[3]);
            }
        }

        if (s == 0)
            epi_diag(c, labels, jb, ibase, m0, n0, lane,
                     li_lo, li_hi, all_lo, all_hi, pos_lo, pos_hi);
        else
            epi_offdiag(c, labels, jb, ibase, m0, n0, lane,
                        li_lo, li_hi, all_lo, all_hi, pos_lo, pos_hi);

        if (t + 1 < nt) {
            CP_WAIT0();
            __syncthreads();
        }
    }

    // reduce row partials across the 4 lanes sharing each row slot
#pragma unroll
    for (int m = 0; m < 4; ++m) {
#pragma unroll
        for (int o = 1; o <= 2; o <<= 1) {
            all_lo[m] += __shfl_xor_sync(0xffffffffu, all_lo[m], o);
            all_hi[m] += __shfl_xor_sync(0xffffffffu, all_hi[m], o);
            pos_lo[m] += __shfl_xor_sync(0xffffffffu, pos_lo[m], o);
            pos_hi[m] += __shfl_xor_sync(0xffffffffu, pos_hi[m], o);
        }
    }
    if ((lane & 3) == 0) {
#pragma unroll
        for (int m = 0; m < 4; ++m) {
            const int rr = ibase + m0 + m * 16 + (lane >> 2);
            atomicAdd(&g_all[rr],     all_lo[m]);
            atomicAdd(&g_pos[rr],     pos_lo[m]);
            atomicAdd(&g_all[rr + 8], all_hi[m]);
            atomicAdd(&g_pos[rr + 8], pos_hi[m]);
        }
    }
}

// ============================ Kernel 3: reduce ============================
__global__ void cpe_final_kernel(const int* __restrict__ labels, float* __restrict__ out) {
    __shared__ float s_sum[1024];
    __shared__ int   s_nv[1024];
    __shared__ int   s_fg[1024];
    float sum = 0.0f; int nv = 0, nfg = 0;
    for (int i = threadIdx.x; i < NROWS; i += 1024) {
        const int lab = labels[i];
        const bool fg = (lab >= 0);
        if (fg) nfg++;
        const float p = g_pos[i];
        const float a = g_all[i];
        if (fg && p > 0.0f) {
            float pc = fminf(fmaxf(p, 1e-6f), 1e6f);
            float ac = fminf(fmaxf(a, 1e-6f), 1e6f);
            sum += fminf(__logf(ac) - __logf(pc), 10.0f);
            nv++;
        }
    }
    s_sum[threadIdx.x] = sum; s_nv[threadIdx.x] = nv; s_fg[threadIdx.x] = nfg;
    __syncthreads();
    for (int o = 512; o > 0; o >>= 1) {
        if (threadIdx.x < o) {
            s_sum[threadIdx.x] += s_sum[threadIdx.x + o];
            s_nv[threadIdx.x]  += s_nv[threadIdx.x + o];
            s_fg[threadIdx.x]  += s_fg[threadIdx.x + o];
        }
        __syncthreads();
    }
    if (threadIdx.x == 0) {
        const int tnv = s_nv[0], tnfg = s_fg[0];
        const float mean = s_sum[0] / (float)(tnv > 0 ? tnv : 1);
        out[0] = (tnfg >= 2 && tnv > 0) ? mean : 0.0f;
    }
}

// ============================================================================
extern "C" void kernel_launch(void* const* d_in, const int* in_sizes, int n_in,
                              void* d_out, int out_size) {
    const float* features = (const float*)d_in[0];
    const int*   labels   = (const int*)d_in[1];
    float*       out      = (float*)d_out;

    cudaFuncSetAttribute(cpe_main_kernel,
                         cudaFuncAttributeMaxDynamicSharedMemorySize, SM_TOTAL);

    cpe_norm_kernel<<<NROWS / 16, 256>>>(features);
    cpe_main_kernel<<<dim3(NTILES, 4), 256, SM_TOTAL>>>(labels);
    cpe_final_kernel<<<1, 1024>>>(labels, out);
}